// round 2
// baseline (speedup 1.0000x reference)
#include <cuda_runtime.h>
#include <cuda_bf16.h>

// Problem constants
#define B_  16
#define C_  4096
#define HD_ 1024   // H*D
#define F_  1024

// Tiling: grid = (NF, NK), block = TFX threads
#define NF  8
#define TFX 128     // f columns per block (== blockDim.x)
#define NK  16
#define TK  64      // k rows per block

// Cross-block reduction scratch. __device__ globals are zero-initialized at
// module load; the finisher block resets them to zero each run, so every
// graph replay starts from the same state.
__device__ float        g_acc[B_ * F_];
__device__ unsigned int g_cnt[NF];

__device__ __forceinline__ float ldcg_f(const float* p) {
    float v;
    asm volatile("ld.global.cg.f32 %0, [%1];" : "=f"(v) : "l"(p));
    return v;
}
__device__ __forceinline__ void stcg_f(float* p, float v) {
    asm volatile("st.global.cg.f32 [%0], %1;" :: "l"(p), "f"(v));
}

// ---------------------------------------------------------------------------
// One fused kernel:
//   attention degenerates to v_sel[b] = bf16( kv_value[b, start] )  (or the
//   fresh x@wv+bv row iff idx==0), and y = v_sel @ wo + bo.
//   Split-K GEMM with device-scope accumulator + last-block-out epilogue.
// ---------------------------------------------------------------------------
__global__ void __launch_bounds__(TFX, 1)
fused_mha_kernel(const float* __restrict__ x,
                 const int*   __restrict__ kv_idx,
                 const float* __restrict__ kv_value,
                 const float* __restrict__ wv,
                 const float* __restrict__ bv,
                 const float* __restrict__ wo,
                 const float* __restrict__ bo,
                 float* __restrict__ y)
{
    const int fx  = blockIdx.x;         // f tile
    const int kx  = blockIdx.y;         // k chunk
    const int tid = threadIdx.x;
    const int k0  = kx * TK;
    const int f   = fx * TFX + tid;

    __shared__ float vs[B_][TK];        // selected v values (bf16-rounded)
    __shared__ float wsm[TK][TFX];      // wo tile, 32KB
    __shared__ int   s_start[B_];
    __shared__ int   s_new[B_];

    if (tid < B_) {
        const int idx     = kv_idx[tid];
        const int new_idx = idx + 1;
        const int start   = (new_idx <= C_) ? 0 : (new_idx % C_);
        s_start[tid] = start;
        s_new[tid]   = (start == (idx % C_));   // only possible when idx==0
    }
    __syncthreads();

    // ---- Stage wo tile [k0:k0+TK, fx*TFX : +TFX] into smem (float4) ----
    {
        const float4* wo4 = reinterpret_cast<const float4*>(
            wo + (size_t)k0 * F_ + fx * TFX);
        #pragma unroll
        for (int i = 0; i < (TK * TFX / 4) / TFX; i++) {   // 16 iters
            const int li = i * TFX + tid;                  // 0..2047
            const int r  = li >> 5;                        // / (TFX/4)
            const int c  = li & 31;
            const float4 v = wo4[(size_t)r * (F_ / 4) + c];
            wsm[r][c * 4 + 0] = v.x;
            wsm[r][c * 4 + 1] = v.y;
            wsm[r][c * 4 + 2] = v.z;
            wsm[r][c * 4 + 3] = v.w;
        }
    }

    // ---- Gather vs[b][k] = bf16(kv_value[b, start_b, k0+k]) ----
    #pragma unroll
    for (int i = tid; i < B_ * TK; i += TFX) {
        const int b = i / TK, k = i % TK;
        if (!s_new[b]) {
            const float v = __ldg(
                &kv_value[((size_t)b * C_ + s_start[b]) * HD_ + k0 + k]);
            vs[b][k] = __bfloat162float(__float2bfloat16(v));
        }
    }
    // Rare fallback (idx==0): fresh row = x[b] @ wv + bv
    for (int b = 0; b < B_; b++) {
        if (s_new[b] && tid < TK) {
            const int j = k0 + tid;
            float acc = bv[j];
            for (int ff = 0; ff < F_; ff++)
                acc = fmaf(__ldg(&x[b * F_ + ff]),
                           __ldg(&wv[(size_t)ff * HD_ + j]), acc);
            vs[b][tid] = __bfloat162float(__float2bfloat16(acc));
        }
    }
    __syncthreads();

    // ---- Main FMA loop: acc[b] += vs[b][k] * wo[k][f] ----
    float acc[B_];
    #pragma unroll
    for (int b = 0; b < B_; b++) acc[b] = 0.0f;

    #pragma unroll 8
    for (int k = 0; k < TK; k++) {
        const float w = wsm[k][tid];
        #pragma unroll
        for (int b = 0; b < B_; b++)
            acc[b] = fmaf(vs[b][k], w, acc[b]);
    }

    // ---- Cross-block reduction into device scratch ----
    #pragma unroll
    for (int b = 0; b < B_; b++)
        atomicAdd(&g_acc[b * F_ + f], acc[b]);

    __threadfence();          // make our partials visible before arrival
    __syncthreads();          // all threads of this block have fenced

    __shared__ int s_last;
    if (tid == 0)
        s_last = (atomicAdd(&g_cnt[fx], 1u) == (NK - 1));
    __syncthreads();

    if (s_last) {
        __threadfence();      // acquire: observe all producers' atomics
        const float bias = bo[f];
        #pragma unroll
        for (int b = 0; b < B_; b++) {
            float* p = &g_acc[b * F_ + f];
            const float v = ldcg_f(p);
            y[b * F_ + f] = v + bias;
            stcg_f(p, 0.0f);  // reset scratch for the next replay
        }
        __threadfence();
        if (tid == 0) atomicExch(&g_cnt[fx], 0u);
    }
}

// ---------------------------------------------------------------------------
// Inputs (metadata order): x, mask, kv_idx, kv_key, kv_value,
//                          wq, bq, wk, bk, wv, bv, wo, bo
// ---------------------------------------------------------------------------
extern "C" void kernel_launch(void* const* d_in, const int* in_sizes, int n_in,
                              void* d_out, int out_size)
{
    const float* x        = (const float*)d_in[0];
    const int*   kv_idx   = (const int*)  d_in[2];
    const float* kv_value = (const float*)d_in[4];
    const float* wv       = (const float*)d_in[9];
    const float* bv       = (const float*)d_in[10];
    const float* wo       = (const float*)d_in[11];
    const float* bo       = (const float*)d_in[12];
    float* y = (float*)d_out;

    fused_mha_kernel<<<dim3(NF, NK), TFX>>>(x, kv_idx, kv_value,
                                            wv, bv, wo, bo, y);
}

// round 3
// speedup vs baseline: 1.6335x; 1.6335x over previous
#include <cuda_runtime.h>
#include <cuda_bf16.h>

// Problem constants
#define B_  16
#define C_  4096
#define HD_ 1024   // H*D
#define F_  1024

// GEMM tiling: grid = (NF, NK), block = TFX threads, 1 f-column per thread
#define NF  8
#define TFX 128
#define NK  32
#define TK  32

// Split-K partials: distinct slot per (k-chunk, b, f). Plain stores, no atomics.
__device__ float g_part[NK][B_][F_];   // 2 MB scratch

// ---------------------------------------------------------------------------
// Kernel 1: partial GEMM. Attention degenerates (T=1 causal ⇒ one-hot at
// rotated position 0) to v_sel[b] = bf16(kv_value[b, start_b]) — or the fresh
// x@wv+bv row iff idx==0. Each block gathers its own TK-slice of v_sel and
// computes g_part[kx][b][f] = sum_{k in chunk} v_sel[b,k] * wo[k,f].
// wo is read straight from global (no cross-thread reuse -> no smem staging).
// ---------------------------------------------------------------------------
__global__ void __launch_bounds__(TFX)
gemm_partial_kernel(const float* __restrict__ x,
                    const int*   __restrict__ kv_idx,
                    const float* __restrict__ kv_value,
                    const float* __restrict__ wv,
                    const float* __restrict__ bv,
                    const float* __restrict__ wo)
{
    const int fx  = blockIdx.x;
    const int kx  = blockIdx.y;
    const int tid = threadIdx.x;
    const int k0  = kx * TK;
    const int f   = fx * TFX + tid;

    __shared__ float vs[B_][TK];    // bf16-rounded selected v slice (k-contig)
    __shared__ int   s_start[B_];
    __shared__ int   s_new[B_];

    if (tid < B_) {
        const int idx     = kv_idx[tid];
        const int new_idx = idx + 1;
        const int start   = (new_idx <= C_) ? 0 : (new_idx % C_);
        s_start[tid] = start;
        s_new[tid]   = (start == (idx % C_));   // only when idx == 0
    }
    __syncthreads();

    // Gather vs[b][k] (512 elems / 128 threads = 4 each, independent loads)
    #pragma unroll
    for (int i = tid; i < B_ * TK; i += TFX) {
        const int b = i / TK, k = i % TK;
        if (!s_new[b]) {
            const float v = __ldg(
                &kv_value[((size_t)b * C_ + s_start[b]) * HD_ + k0 + k]);
            vs[b][k] = __bfloat162float(__float2bfloat16(v));
        }
    }
    // Rare fallback (idx==0): fresh row = x[b] @ wv + bv for this k-slice
    for (int b = 0; b < B_; b++) {
        if (s_new[b] && tid < TK) {
            const int j = k0 + tid;
            float acc = bv[j];
            for (int ff = 0; ff < F_; ff++)
                acc = fmaf(__ldg(&x[b * F_ + ff]),
                           __ldg(&wv[(size_t)ff * HD_ + j]), acc);
            vs[b][tid] = __bfloat162float(__float2bfloat16(acc));
        }
    }
    __syncthreads();

    float acc[B_];
    #pragma unroll
    for (int b = 0; b < B_; b++) acc[b] = 0.0f;

    // Main loop: 4 k's at a time. wo from global (coalesced 128B per warp
    // per load, k-unrolled for MLP), vs via conflict-free LDS.128 broadcast.
    #pragma unroll
    for (int k4 = 0; k4 < TK; k4 += 4) {
        const float w0 = __ldg(&wo[(size_t)(k0 + k4 + 0) * F_ + f]);
        const float w1 = __ldg(&wo[(size_t)(k0 + k4 + 1) * F_ + f]);
        const float w2 = __ldg(&wo[(size_t)(k0 + k4 + 2) * F_ + f]);
        const float w3 = __ldg(&wo[(size_t)(k0 + k4 + 3) * F_ + f]);
        #pragma unroll
        for (int b = 0; b < B_; b++) {
            const float4 v = *reinterpret_cast<const float4*>(&vs[b][k4]);
            acc[b] = fmaf(v.x, w0,
                     fmaf(v.y, w1,
                     fmaf(v.z, w2,
                     fmaf(v.w, w3, acc[b]))));
        }
    }

    // Coalesced partial stores to distinct slots (no atomics)
    #pragma unroll
    for (int b = 0; b < B_; b++)
        g_part[kx][b][f] = acc[b];
}

// ---------------------------------------------------------------------------
// Kernel 2: reduce partials + bias. y[b,f] = bo[f] + sum_kx g_part[kx][b][f]
// 32 independent loads per thread (MLP=32), coalesced within warps.
// ---------------------------------------------------------------------------
__global__ void __launch_bounds__(256)
reduce_kernel(const float* __restrict__ bo, float* __restrict__ y)
{
    const int i = blockIdx.x * 256 + threadIdx.x;   // i = b*F_ + f
    const int f = i & (F_ - 1);
    const int b = i >> 10;

    float sum = bo[f];
    #pragma unroll
    for (int kx = 0; kx < NK; kx++)
        sum += g_part[kx][b][f];
    y[i] = sum;
}

// ---------------------------------------------------------------------------
// Inputs (metadata order): x, mask, kv_idx, kv_key, kv_value,
//                          wq, bq, wk, bk, wv, bv, wo, bo
// ---------------------------------------------------------------------------
extern "C" void kernel_launch(void* const* d_in, const int* in_sizes, int n_in,
                              void* d_out, int out_size)
{
    const float* x        = (const float*)d_in[0];
    const int*   kv_idx   = (const int*)  d_in[2];
    const float* kv_value = (const float*)d_in[4];
    const float* wv       = (const float*)d_in[9];
    const float* bv       = (const float*)d_in[10];
    const float* wo       = (const float*)d_in[11];
    const float* bo       = (const float*)d_in[12];
    float* y = (float*)d_out;

    gemm_partial_kernel<<<dim3(NF, NK), TFX>>>(x, kv_idx, kv_value, wv, bv, wo);
    reduce_kernel<<<(B_ * F_) / 256, 256>>>(bo, y);
}